// round 7
// baseline (speedup 1.0000x reference)
#include <cuda_runtime.h>
#include <math.h>
#include <stddef.h>

// ---------------------------------------------------------------------------
// GeometricCrossAttentionBlock — fp32 baseline
//   streams: 0 = src (tokens 0..4095), 1 = tgt (tokens 4096..8191)
//   d_out doubles as the running residual buffer "cur" [8192][256]
// ---------------------------------------------------------------------------

#define TOKS   8192
#define DIMM   256
#define NSEQ   1024
#define NHEAD  8
#define HDIM   32
#define FFND   1024
#define ATT_SCALE 0.17677669529663687f   /* 32^-0.5 */

// -------------------- device scratch (allocation-free rule) ----------------
__device__ float g_xn [TOKS * DIMM];            //  8 MB   LN output
__device__ float g_q  [TOKS * DIMM];            //  8 MB
__device__ float g_k  [TOKS * DIMM];            //  8 MB
__device__ float g_v  [TOKS * DIMM];            //  8 MB
__device__ float g_att[TOKS * DIMM];            //  8 MB   attention out (pre O-proj)
__device__ float g_h  [TOKS * FFND];            // 32 MB   FFN hidden
__device__ float g_scores[67108864];            // 256 MB  [2][4][8][1024][1024]

// ---------------------------------------------------------------------------
// LayerNorm over last dim (256). One block (256 thr) per row.
// ---------------------------------------------------------------------------
__global__ void __launch_bounds__(256) ln_kernel(
    const float* __restrict__ in, const float* __restrict__ g,
    const float* __restrict__ b, float* __restrict__ out)
{
    int t = blockIdx.x;
    int c = threadIdx.x;
    float x = in[(size_t)t * DIMM + c];
    float s = x, sq = x * x;
    #pragma unroll
    for (int o = 16; o; o >>= 1) {
        s  += __shfl_xor_sync(0xFFFFFFFFu, s,  o);
        sq += __shfl_xor_sync(0xFFFFFFFFu, sq, o);
    }
    __shared__ float sh1[8], sh2[8];
    int w = c >> 5, l = c & 31;
    if (l == 0) { sh1[w] = s; sh2[w] = sq; }
    __syncthreads();
    if (w == 0) {
        s = sh1[l & 7]; sq = sh2[l & 7];
        #pragma unroll
        for (int o = 4; o; o >>= 1) {
            s  += __shfl_xor_sync(0xFFFFFFFFu, s,  o);
            sq += __shfl_xor_sync(0xFFFFFFFFu, sq, o);
        }
        if (l == 0) { sh1[0] = s; sh2[0] = sq; }
    }
    __syncthreads();
    float mean = sh1[0] * (1.0f / DIMM);
    float var  = sh2[0] * (1.0f / DIMM) - mean * mean;
    float rstd = rsqrtf(var + 1e-5f);
    out[(size_t)t * DIMM + c] = (x - mean) * rstd * g[c] + b[c];
}

// ---------------------------------------------------------------------------
// Generic GEMM: C[8192 x Nc] = A[8192 x K] @ W[K x Nc] + bias
//   optional exact GELU epilogue, optional residual accumulate (C += ...)
//   block tile 128x64, 256 threads, 8x4 outputs/thread, K-tile 16.
// ---------------------------------------------------------------------------
template<int K, bool DOGELU, bool RES>
__global__ void __launch_bounds__(256) gemm_kernel(
    const float* __restrict__ A, const float* __restrict__ W,
    const float* __restrict__ bias, float* __restrict__ C, int Nc)
{
    __shared__ __align__(16) float AsT[16][132];  // [k][m], padded
    __shared__ __align__(16) float Ws [16][64];   // [k][n]
    int tid = threadIdx.x;
    int tx = tid & 15, ty = tid >> 4;
    int m0 = blockIdx.y * 128;
    int n0 = blockIdx.x * 64;

    float acc[8][4];
    #pragma unroll
    for (int i = 0; i < 8; ++i)
        #pragma unroll
        for (int j = 0; j < 4; ++j) acc[i][j] = 0.0f;

    for (int kt = 0; kt < K / 16; ++kt) {
        int k0 = kt * 16;
        #pragma unroll
        for (int p = 0; p < 2; ++p) {                 // A tile 128x16 -> AsT
            int qi = tid + p * 256;
            int r = qi >> 2, c4 = qi & 3;
            float4 a = *(const float4*)(A + (size_t)(m0 + r) * K + k0 + c4 * 4);
            AsT[c4 * 4 + 0][r] = a.x; AsT[c4 * 4 + 1][r] = a.y;
            AsT[c4 * 4 + 2][r] = a.z; AsT[c4 * 4 + 3][r] = a.w;
        }
        {                                             // W tile 16x64
            int kk = tid >> 4, c4 = tid & 15;
            *(float4*)&Ws[kk][c4 * 4] =
                *(const float4*)(W + (size_t)(k0 + kk) * Nc + n0 + c4 * 4);
        }
        __syncthreads();
        #pragma unroll
        for (int kk = 0; kk < 16; ++kk) {
            float4 b4 = *(float4*)&Ws[kk][tx * 4];
            float4 a0 = *(float4*)&AsT[kk][ty * 8];
            float4 a1 = *(float4*)&AsT[kk][ty * 8 + 4];
            float av[8] = {a0.x, a0.y, a0.z, a0.w, a1.x, a1.y, a1.z, a1.w};
            float bv[4] = {b4.x, b4.y, b4.z, b4.w};
            #pragma unroll
            for (int i = 0; i < 8; ++i)
                #pragma unroll
                for (int j = 0; j < 4; ++j)
                    acc[i][j] = fmaf(av[i], bv[j], acc[i][j]);
        }
        __syncthreads();
    }

    #pragma unroll
    for (int i = 0; i < 8; ++i) {
        int r = m0 + ty * 8 + i;
        #pragma unroll
        for (int j = 0; j < 4; ++j) {
            int cc = n0 + tx * 4 + j;
            float val = acc[i][j] + bias[cc];
            if (DOGELU) val = 0.5f * val * (1.0f + erff(val * 0.70710678118654752f));
            size_t idx = (size_t)r * Nc + cc;
            if (RES) val += C[idx];
            C[idx] = val;
        }
    }
}

// ---------------------------------------------------------------------------
// Scores: S[z, n, m] = SCALE * q[n,:] . k[m,:] (+ geo bias), z = (s*4+b)*8+h
//   64x64 output tile per block, full K=32 head dim in smem.
// ---------------------------------------------------------------------------
__global__ void __launch_bounds__(256) scores_kernel(
    const float* __restrict__ Q, const float* __restrict__ Km,
    const float* __restrict__ biasS, const float* __restrict__ biasT,
    float* __restrict__ S, int kv_swap)
{
    __shared__ __align__(16) float QsT[32][68];   // [d][n]
    __shared__ __align__(16) float KsT[32][68];   // [d][m]
    int tid = threadIdx.x;
    int mt = blockIdx.x, nt = blockIdx.y, z = blockIdx.z;
    int s = z >> 5, bh = z & 31, b = bh >> 3, h = bh & 7;
    int qb = s * 4096 + b * 1024 + nt * 64;
    int ks = kv_swap ? (1 - s) : s;
    int kb = ks * 4096 + b * 1024 + mt * 64;

    #pragma unroll
    for (int p = 0; p < 2; ++p) {
        int qi = tid + p * 256;
        int r = qi >> 3, c4 = qi & 7;
        float4 a = *(const float4*)(Q  + (size_t)(qb + r) * DIMM + h * 32 + c4 * 4);
        QsT[c4 * 4 + 0][r] = a.x; QsT[c4 * 4 + 1][r] = a.y;
        QsT[c4 * 4 + 2][r] = a.z; QsT[c4 * 4 + 3][r] = a.w;
        float4 kk = *(const float4*)(Km + (size_t)(kb + r) * DIMM + h * 32 + c4 * 4);
        KsT[c4 * 4 + 0][r] = kk.x; KsT[c4 * 4 + 1][r] = kk.y;
        KsT[c4 * 4 + 2][r] = kk.z; KsT[c4 * 4 + 3][r] = kk.w;
    }
    __syncthreads();

    int tx = tid & 15, ty = tid >> 4;
    float acc[4][4];
    #pragma unroll
    for (int i = 0; i < 4; ++i)
        #pragma unroll
        for (int j = 0; j < 4; ++j) acc[i][j] = 0.0f;

    #pragma unroll
    for (int d = 0; d < 32; ++d) {
        float4 a = *(float4*)&QsT[d][ty * 4];
        float4 c = *(float4*)&KsT[d][tx * 4];
        float av[4] = {a.x, a.y, a.z, a.w};
        float cv[4] = {c.x, c.y, c.z, c.w};
        #pragma unroll
        for (int i = 0; i < 4; ++i)
            #pragma unroll
            for (int j = 0; j < 4; ++j)
                acc[i][j] = fmaf(av[i], cv[j], acc[i][j]);
    }

    const float* bias = (biasS == nullptr) ? nullptr : ((s == 0) ? biasS : biasT);
    #pragma unroll
    for (int i = 0; i < 4; ++i) {
        int n = nt * 64 + ty * 4 + i;
        #pragma unroll
        for (int j = 0; j < 4; ++j) {
            int m = mt * 64 + tx * 4 + j;
            float val = acc[i][j] * ATT_SCALE;
            if (bias)
                val += bias[((size_t)(b * NHEAD + h) * NSEQ + n) * NSEQ + m];
            S[((size_t)z * NSEQ + n) * NSEQ + m] = val;
        }
    }
}

// ---------------------------------------------------------------------------
// Softmax over last dim (1024), in place. One warp per row, 8 warps/block.
// ---------------------------------------------------------------------------
__global__ void __launch_bounds__(256) softmax_kernel(float* __restrict__ S)
{
    int warp = threadIdx.x >> 5, lane = threadIdx.x & 31;
    size_t row = (size_t)blockIdx.x * 8 + warp;
    float* p = S + row * NSEQ;

    float4 v[8];
    #pragma unroll
    for (int u = 0; u < 8; ++u) v[u] = *(float4*)(p + (lane + u * 32) * 4);

    float mx = -1e30f;
    #pragma unroll
    for (int u = 0; u < 8; ++u) {
        mx = fmaxf(mx, fmaxf(fmaxf(v[u].x, v[u].y), fmaxf(v[u].z, v[u].w)));
    }
    #pragma unroll
    for (int o = 16; o; o >>= 1) mx = fmaxf(mx, __shfl_xor_sync(0xFFFFFFFFu, mx, o));

    float sum = 0.0f;
    #pragma unroll
    for (int u = 0; u < 8; ++u) {
        v[u].x = __expf(v[u].x - mx); v[u].y = __expf(v[u].y - mx);
        v[u].z = __expf(v[u].z - mx); v[u].w = __expf(v[u].w - mx);
        sum += v[u].x + v[u].y + v[u].z + v[u].w;
    }
    #pragma unroll
    for (int o = 16; o; o >>= 1) sum += __shfl_xor_sync(0xFFFFFFFFu, sum, o);

    float r = 1.0f / sum;
    #pragma unroll
    for (int u = 0; u < 8; ++u) {
        v[u].x *= r; v[u].y *= r; v[u].z *= r; v[u].w *= r;
        *(float4*)(p + (lane + u * 32) * 4) = v[u];
    }
}

// ---------------------------------------------------------------------------
// PV: out[n, h*32+d] = sum_m P[z,n,m] * v[m, h*32+d]
//   64 rows x 32 cols per block (full head dim), K-tiles of 32.
// ---------------------------------------------------------------------------
__global__ void __launch_bounds__(256) pv_kernel(
    const float* __restrict__ S, const float* __restrict__ V,
    float* __restrict__ O, int kv_swap)
{
    __shared__ __align__(16) float PsT[32][68];   // [m][n]
    __shared__ __align__(16) float Vs [32][32];   // [m][d]
    int tid = threadIdx.x;
    int nt = blockIdx.x, z = blockIdx.y;
    int s = z >> 5, bh = z & 31, b = bh >> 3, h = bh & 7;
    int qb  = s * 4096 + b * 1024;
    int ks  = kv_swap ? (1 - s) : s;
    int kvb = ks * 4096 + b * 1024;
    int tx = tid & 31, ty = tid >> 5;

    float acc[8];
    #pragma unroll
    for (int i = 0; i < 8; ++i) acc[i] = 0.0f;

    const float* Srow = S + ((size_t)z * NSEQ + nt * 64) * NSEQ;

    for (int mt = 0; mt < 32; ++mt) {
        #pragma unroll
        for (int p = 0; p < 2; ++p) {
            int qi = tid + p * 256;
            int r = qi >> 3, c4 = qi & 7;
            float4 a = *(const float4*)(Srow + (size_t)r * NSEQ + mt * 32 + c4 * 4);
            PsT[c4 * 4 + 0][r] = a.x; PsT[c4 * 4 + 1][r] = a.y;
            PsT[c4 * 4 + 2][r] = a.z; PsT[c4 * 4 + 3][r] = a.w;
        }
        {
            int r = tid >> 3, c4 = tid & 7;
            *(float4*)&Vs[r][c4 * 4] =
                *(const float4*)(V + (size_t)(kvb + mt * 32 + r) * DIMM + h * 32 + c4 * 4);
        }
        __syncthreads();
        #pragma unroll
        for (int mk = 0; mk < 32; ++mk) {
            float vv = Vs[mk][tx];
            float4 p0 = *(float4*)&PsT[mk][ty * 8];
            float4 p1 = *(float4*)&PsT[mk][ty * 8 + 4];
            acc[0] = fmaf(p0.x, vv, acc[0]); acc[1] = fmaf(p0.y, vv, acc[1]);
            acc[2] = fmaf(p0.z, vv, acc[2]); acc[3] = fmaf(p0.w, vv, acc[3]);
            acc[4] = fmaf(p1.x, vv, acc[4]); acc[5] = fmaf(p1.y, vv, acc[5]);
            acc[6] = fmaf(p1.z, vv, acc[6]); acc[7] = fmaf(p1.w, vv, acc[7]);
        }
        __syncthreads();
    }
    #pragma unroll
    for (int i = 0; i < 8; ++i)
        O[(size_t)(qb + nt * 64 + ty * 8 + i) * DIMM + h * 32 + tx] = acc[i];
}

// ---------------------------------------------------------------------------
// Host orchestration
// ---------------------------------------------------------------------------
extern "C" void kernel_launch(void* const* d_in, const int* in_sizes, int n_in,
                              void* d_out, int out_size)
{
    (void)in_sizes; (void)n_in; (void)out_size;

    const float* src   = (const float*)d_in[0];
    const float* tgt   = (const float*)d_in[1];
    const float* biasS = (const float*)d_in[2];
    const float* biasT = (const float*)d_in[3];
    // 4..11: sa q_w,q_b,k_w,k_b,v_w,v_b,o_w,o_b ; 12..19: ca same
    // 20..25: ln_sa_g, ln_sa_b, ln_ca_g, ln_ca_b, ln_ff_g, ln_ff_b
    // 26..29: ffn_w1, ffn_b1, ffn_w2, ffn_b2
    #define IN(i) ((const float*)d_in[(i)])

    float *xn, *q, *k, *v, *att, *hbuf, *sc;
    cudaGetSymbolAddress((void**)&xn,   g_xn);
    cudaGetSymbolAddress((void**)&q,    g_q);
    cudaGetSymbolAddress((void**)&k,    g_k);
    cudaGetSymbolAddress((void**)&v,    g_v);
    cudaGetSymbolAddress((void**)&att,  g_att);
    cudaGetSymbolAddress((void**)&hbuf, g_h);
    cudaGetSymbolAddress((void**)&sc,   g_scores);

    float* cur = (float*)d_out;     // running residual; stream 0 then stream 1
    size_t half = (size_t)4096 * DIMM * sizeof(float);
    cudaMemcpyAsync(cur, src, half, cudaMemcpyDeviceToDevice);
    cudaMemcpyAsync(cur + (size_t)4096 * DIMM, tgt, half, cudaMemcpyDeviceToDevice);

    dim3 gProj(4, 64);      // Nc=256 GEMMs over 8192 tokens
    dim3 gFfn1(16, 64);     // Nc=1024
    dim3 gScore(16, 16, 64);
    dim3 gPV(16, 64);

    // ---- stage 1: geometric self-attention (pre-norm residual) ----
    ln_kernel<<<TOKS, 256>>>(cur, IN(20), IN(21), xn);
    gemm_kernel<256, false, false><<<gProj, 256>>>(xn, IN(4),  IN(5),  q, 256);
    gemm_kernel<256, false, false><<<gProj, 256>>>(xn, IN(6),  IN(7),  k, 256);
    gemm_kernel<256, false, false><<<gProj, 256>>>(xn, IN(8),  IN(9),  v, 256);
    scores_kernel<<<gScore, 256>>>(q, k, biasS, biasT, sc, 0);
    softmax_kernel<<<TOKS, 256>>>(sc);
    pv_kernel<<<gPV, 256>>>(sc, v, att, 0);
    gemm_kernel<256, false, true><<<gProj, 256>>>(att, IN(10), IN(11), cur, 256);

    // ---- stage 2: cross-attention (kv from the other stream) ----
    ln_kernel<<<TOKS, 256>>>(cur, IN(22), IN(23), xn);
    gemm_kernel<256, false, false><<<gProj, 256>>>(xn, IN(12), IN(13), q, 256);
    gemm_kernel<256, false, false><<<gProj, 256>>>(xn, IN(14), IN(15), k, 256);
    gemm_kernel<256, false, false><<<gProj, 256>>>(xn, IN(16), IN(17), v, 256);
    scores_kernel<<<gScore, 256>>>(q, k, nullptr, nullptr, sc, 1);
    softmax_kernel<<<TOKS, 256>>>(sc);
    pv_kernel<<<gPV, 256>>>(sc, v, att, 1);
    gemm_kernel<256, false, true><<<gProj, 256>>>(att, IN(18), IN(19), cur, 256);

    // ---- stage 3: FFN ----
    ln_kernel<<<TOKS, 256>>>(cur, IN(24), IN(25), xn);
    gemm_kernel<256,  true,  false><<<gFfn1, 256>>>(xn,   IN(26), IN(27), hbuf, 1024);
    gemm_kernel<1024, false, true ><<<gProj, 256>>>(hbuf, IN(28), IN(29), cur,  256);

    #undef IN
}